// round 6
// baseline (speedup 1.0000x reference)
#include <cuda_runtime.h>

#define HH 96
#define WW 128
#define CC 21
#define RR 14
#define ITERS 5
#define NBLK 96
#define NTHR 672          // 21 warps: warp = channel, lane = x-quad (phase A)
#define PH (HH + 2*RR)    // 124 padded rows
#define SPW 160           // padded prob-row floats: 14 | 128 | 14 | 4 spare

// single-buffered planes (all WAR hazards separated by the two grid barriers)
__device__ float4 g_t[CC][PH*32];    // blur-x(A*p)*nxinv, zero-padded rows
__device__ float4 g_q[CC][HH*32];    // q plane
__device__ float4 g_u[CC][HH*32];    // transposed unaries
__device__ unsigned g_barcnt[2*ITERS + 1];

// cumulative-ticket grid barrier: replay-safe (each replay adds exactly NBLK
// arrivals per counter), wrap-safe (signed compare).
__device__ __forceinline__ void gridbar(int k) {
    __syncthreads();
    __threadfence();
    if (threadIdx.x == 0) {
        unsigned t = atomicAdd(&g_barcnt[k], 1u);
        unsigned target = t - (t % (unsigned)NBLK) + (unsigned)NBLK;
        volatile unsigned* pc = &g_barcnt[k];
        while ((int)(*pc - target) < 0) { }
        __threadfence();
    }
    __syncthreads();
}

__global__ void __launch_bounds__(NTHR, 1) crf_persistent(
    const float* __restrict__ un, const float* __restrict__ ws,
    const float* __restrict__ wb, const float* __restrict__ comp,
    float* __restrict__ out)
{
    // exp(-d*d/18) taps as literals -> FFMA-imm (rt=1)
    const float w[15] = {
        1.0f, 0.9459594f, 0.8007374f, 0.6065307f, 0.4111123f,
        0.2493522f, 0.1353353f, 0.0657285f, 0.0285655f, 0.0111090f,
        0.0038659f, 0.0012039f, 0.00033546f, 0.00008365f, 0.00001866f };

    __shared__ __align__(16) float  sp[CC][SPW];   // r = A*p rows, zero-padded in x
    __shared__ __align__(16) float4 sv[CC][32];    // exp(q) exchange
    __shared__ __align__(16) float  sA[CC][CC];    // A = compat @ (Ws+Wb)
    __shared__ __align__(16) float  tile[PH][32];  // phase-B column tile
    __shared__ __align__(16) float  snyi[HH];

    const int tid = threadIdx.x;
    const int c   = tid >> 5;             // phase-A warp = channel
    const int l   = tid & 31;             // lane = x-quad
    const int y   = blockIdx.x;

    // ---- one-time init ----
    if (l < CC) {                         // warp c computes A row c
        float a = 0.f;
        #pragma unroll
        for (int k = 0; k < CC; k++)
            a += comp[c*CC + k] * (ws[k*CC + l] + wb[k*CC + l]);
        sA[c][l] = a;
    }
    if (l < RR) { sp[c][l] = 0.f; sp[c][RR + WW + l] = 0.f; }
    if (tid < HH) {
        float s = 0.f;
        #pragma unroll
        for (int d = -RR; d <= RR; d++) {
            int ad = d < 0 ? -d : d;
            if ((unsigned)(tid + d) < HH) s += w[ad];
        }
        snyi[tid] = 1.0f / s;
    }
    // zero g_t pad rows (grid-strided, once; interior rows overwritten each iter)
    {
        float4 z = {0.f,0.f,0.f,0.f};
        for (int idx = blockIdx.x*NTHR + tid; idx < CC*2*RR*32; idx += NBLK*NTHR) {
            int ll = idx & 31;
            int r  = (idx >> 5) % (2*RR);
            int cc = (idx >> 5) / (2*RR);
            int pr = (r < RR) ? r : r + HH;
            g_t[cc][pr*32 + ll] = z;
        }
    }
    // transpose unaries into planes; q = u  (CC*HH*32 == NBLK*NTHR exactly)
    {
        int idx = blockIdx.x*NTHR + tid;
        int ll = idx & 31, yy = (idx >> 5) % HH, cc = (idx >> 5) / HH;
        float4 v;
        v.x = un[(yy*WW + 4*ll + 0)*CC + cc];
        v.y = un[(yy*WW + 4*ll + 1)*CC + cc];
        v.z = un[(yy*WW + 4*ll + 2)*CC + cc];
        v.w = un[(yy*WW + 4*ll + 3)*CC + cc];
        g_u[cc][yy*32 + ll] = v;
        g_q[cc][yy*32 + ll] = v;
    }
    // phase-A x normalizers (truncated sums matching blur truncation)
    float4 nxi;
    {
        float s[4];
        #pragma unroll
        for (int j = 0; j < 4; j++) {
            int x = 4*l + j; float t = 0.f;
            #pragma unroll
            for (int d = -RR; d <= RR; d++) {
                int ad = d < 0 ? -d : d;
                if ((unsigned)(x + d) < WW) t += w[ad];
            }
            s[j] = 1.0f / t;
        }
        nxi.x = s[0]; nxi.y = s[1]; nxi.z = s[2]; nxi.w = s[3];
    }
    gridbar(2*ITERS);   // init visible everywhere

    // ---- CRF iterations ----
    for (int it = 0; it < ITERS; it++) {
        // ===== phase A: row ownership (block = image row) =====
        float4 q4 = __ldcg(&g_q[c][y*32 + l]);
        float4 e4;
        e4.x = __expf(q4.x); e4.y = __expf(q4.y);
        e4.z = __expf(q4.z); e4.w = __expf(q4.w);
        sv[c][l] = e4;
        __syncthreads();

        // fused softmax-sum + matvec:  r = (A @ e) * inv(sum e)  == A @ softmax(q)
        float4 sm = {0.f,0.f,0.f,0.f}, r4 = {0.f,0.f,0.f,0.f};
        #pragma unroll
        for (int c2 = 0; c2 < CC; c2++) {
            float4 v = sv[c2][l];
            float  a = sA[c][c2];
            sm.x += v.x; sm.y += v.y; sm.z += v.z; sm.w += v.w;
            r4.x += a*v.x; r4.y += a*v.y; r4.z += a*v.z; r4.w += a*v.w;
        }
        sp[c][RR + 4*l + 0] = r4.x * __frcp_rn(sm.x);
        sp[c][RR + 4*l + 1] = r4.y * __frcp_rn(sm.y);
        sp[c][RR + 4*l + 2] = r4.z * __frcp_rn(sm.z);
        sp[c][RR + 4*l + 3] = r4.w * __frcp_rn(sm.w);
        __syncthreads();

        // blur-x: aligned 32-float window via 8 LDS.128, taps as immediates
        float win[32];
        {
            const float4* rowp = (const float4*)&sp[c][0];
            #pragma unroll
            for (int k = 0; k < 8; k++) {
                float4 v = rowp[l + k];
                win[4*k+0] = v.x; win[4*k+1] = v.y;
                win[4*k+2] = v.z; win[4*k+3] = v.w;
            }
        }
        float4 acc = {0.f,0.f,0.f,0.f};
        #pragma unroll
        for (int dd = 0; dd <= 28; dd++) {
            float cw = w[dd < RR ? RR - dd : dd - RR];
            acc.x += cw * win[dd];
            acc.y += cw * win[dd + 1];
            acc.z += cw * win[dd + 2];
            acc.w += cw * win[dd + 3];
        }
        acc.x *= nxi.x; acc.y *= nxi.y; acc.z *= nxi.z; acc.w *= nxi.w;
        g_t[c][(y + RR)*32 + l] = acc;

        gridbar(2*it);

        // ===== phase B: (channel, 32-col strip) ownership, 84 active blocks =====
        const int bc = blockIdx.x >> 2;       // channel 0..20
        const int st = blockIdx.x & 3;        // strip 0..3
        if (blockIdx.x < 84) {
            const float4* tsrc = &g_t[bc][0];
            float4* tile4 = (float4*)&tile[0][0];
            for (int i = tid; i < PH*8; i += NTHR) {
                int r = i >> 3, j = i & 7;
                tile4[r*8 + j] = __ldcg(&tsrc[r*32 + st*8 + j]);
            }
        }
        __syncthreads();
        if (blockIdx.x < 84 && tid < 512) {
            const int x   = tid & 31;
            const int seg = tid >> 5;         // 0..15
            const int y0  = seg * 6;
            float col[34];
            #pragma unroll
            for (int k = 0; k < 34; k++) col[k] = tile[y0 + k][x];

            const float* uf = (const float*)&g_u[bc][0];
            float*       qf = (float*)&g_q[bc][0];
            #pragma unroll
            for (int j = 0; j < 6; j++) {
                float a = 0.f;
                #pragma unroll
                for (int dd = 0; dd <= 28; dd++)
                    a += w[dd < RR ? RR - dd : dd - RR] * col[j + dd];
                const int yy = y0 + j;
                const float s = a * snyi[yy];
                const int pidx = yy*WW + st*32 + x;
                if (it < ITERS-1) {
                    qf[pidx] = uf[pidx] - s;
                } else {
                    const int x_img = st*32 + x;
                    out[(x_img*HH + yy)*CC + bc] = uf[pidx] - s;  // (1,W,H,C)
                }
            }
        }
        if (it < ITERS-1) gridbar(2*it + 1);
    }
}

extern "C" void kernel_launch(void* const* d_in, const int* in_sizes, int n_in,
                              void* d_out, int out_size) {
    const float* un   = (const float*)d_in[0];
    // d_in[1] (rgb) is dead: reference uses spatial_out for both message terms
    const float* ws   = (const float*)d_in[2];
    const float* wb   = (const float*)d_in[3];
    const float* comp = (const float*)d_in[4];
    crf_persistent<<<NBLK, NTHR>>>(un, ws, wb, comp, (float*)d_out);
}

// round 7
// speedup vs baseline: 1.2919x; 1.2919x over previous
#include <cuda_runtime.h>

#define HH 96
#define WW 128
#define CC 21
#define RR 14
#define ITERS 5
#define NBLK 96
#define NTHR 672           // 21 warps: warp = channel, lane = x-quad
#define PH (HH + 2*RR)     // 124 padded rows
#define SPW 160            // padded row floats: 14 | 128 | 14 | 4 spare

// double-buffered blur-x(A*p)/nx output, [buf][c][padded_row][x-quad], pad rows zero
__device__ float4 g_t[2][CC][PH*32];
// cumulative per-row completion flags (only block y writes flag[y]; replay-safe)
__device__ unsigned g_rowflag[HH];

__global__ void __launch_bounds__(NTHR, 1) crf_persistent(
    const float* __restrict__ un, const float* __restrict__ ws,
    const float* __restrict__ wb, const float* __restrict__ comp,
    float* __restrict__ out)
{
    // exp(-d*d/18) taps as literals -> FFMA-imm (rt=1)
    const float w[15] = {
        1.0f, 0.9459594f, 0.8007374f, 0.6065307f, 0.4111123f,
        0.2493522f, 0.1353353f, 0.0657285f, 0.0285655f, 0.0111090f,
        0.0038659f, 0.0012039f, 0.00033546f, 0.00008365f, 0.00001866f };

    __shared__ __align__(16) float  sp[CC][SPW];  // r = A*p rows, zero-padded in x
    __shared__ __align__(16) float4 sv[CC][32];   // exp(q) exchange
    __shared__ __align__(16) float  sA[CC][CC];   // A = compat @ (Ws+Wb)

    const int tid = threadIdx.x;
    const int c   = tid >> 5;          // warp = channel 0..20
    const int l   = tid & 31;          // lane = x-quad, pixels 4l..4l+3
    const int y   = blockIdx.x;

    // flag base: all rows equal at launch start (each launch adds exactly ITERS)
    const unsigned base = g_rowflag[y];

    // ---- one-time init ----
    if (l < CC) {                      // warp c computes A row c
        float a = 0.f;
        #pragma unroll
        for (int k = 0; k < CC; k++)
            a += comp[c*CC + k] * (ws[k*CC + l] + wb[k*CC + l]);
        sA[c][l] = a;
    }
    if (l < RR) { sp[c][l] = 0.f; sp[c][RR + WW + l] = 0.f; }

    // zero OWN pad rows (both buffers): block y<14 owns top pad row y;
    // block y>=82 owns bottom pad row y+28. Every reader of a pad row has its
    // owner inside the [y-14, y+14] wait window, so the iter-0 flag wait
    // (fenced bump) also publishes these zeros.
    {
        int pr = -1;
        if (y < RR)            pr = y;
        else if (y >= HH - RR) pr = y + 2*RR;       // 82..95 -> 110..123
        if (pr >= 0) {
            float4 z = {0.f, 0.f, 0.f, 0.f};
            for (int i = tid; i < 2*CC*32; i += NTHR) {
                int b  = (i >= CC*32) ? 1 : 0;
                int r  = i - b*CC*32;
                int cc = r >> 5, ll = r & 31;
                g_t[b][cc][pr*32 + ll] = z;
            }
        }
    }
    // x normalizers (truncated sums matching blur truncation)
    float4 nxi;
    {
        float s[4];
        #pragma unroll
        for (int j = 0; j < 4; j++) {
            int x = 4*l + j; float t = 0.f;
            #pragma unroll
            for (int d = -RR; d <= RR; d++) {
                int ad = d < 0 ? -d : d;
                if ((unsigned)(x + d) < WW) t += w[ad];
            }
            s[j] = 1.0f / t;
        }
        nxi.x = s[0]; nxi.y = s[1]; nxi.z = s[2]; nxi.w = s[3];
    }
    float ny = 0.f;
    #pragma unroll
    for (int d = -RR; d <= RR; d++) {
        int ad = d < 0 ? -d : d;
        if ((unsigned)(y + d) < HH) ny += w[ad];
    }
    const float nyi = 1.0f / ny;

    // unaries -> registers (q never leaves registers)
    float4 u4, q4;
    u4.x = un[(y*WW + 4*l + 0)*CC + c];
    u4.y = un[(y*WW + 4*l + 1)*CC + c];
    u4.z = un[(y*WW + 4*l + 2)*CC + c];
    u4.w = un[(y*WW + 4*l + 3)*CC + c];
    q4 = u4;
    __syncthreads();

    // ---- CRF iterations ----
    for (int it = 0; it < ITERS; it++) {
        float4* tb = &g_t[it & 1][0][0];

        // exp(q) exchange (no max-sub: q stays far below exp overflow)
        float4 e4;
        e4.x = __expf(q4.x); e4.y = __expf(q4.y);
        e4.z = __expf(q4.z); e4.w = __expf(q4.w);
        sv[c][l] = e4;
        __syncthreads();

        // fused softmax-sum + matvec: r = (A @ e) * inv(sum e) == A @ softmax(q)
        float4 sm = {0.f,0.f,0.f,0.f}, r4 = {0.f,0.f,0.f,0.f};
        #pragma unroll
        for (int c2 = 0; c2 < CC; c2++) {
            float4 v = sv[c2][l];
            float  a = sA[c][c2];
            sm.x += v.x; sm.y += v.y; sm.z += v.z; sm.w += v.w;
            r4.x += a*v.x; r4.y += a*v.y; r4.z += a*v.z; r4.w += a*v.w;
        }
        sp[c][RR + 4*l + 0] = r4.x * __frcp_rn(sm.x);
        sp[c][RR + 4*l + 1] = r4.y * __frcp_rn(sm.y);
        sp[c][RR + 4*l + 2] = r4.z * __frcp_rn(sm.z);
        sp[c][RR + 4*l + 3] = r4.w * __frcp_rn(sm.w);
        __syncthreads();

        // blur-x: aligned 32-float window via 8 LDS.128, taps as immediates
        float win[32];
        {
            const float4* rowp = (const float4*)&sp[c][0];
            #pragma unroll
            for (int k = 0; k < 8; k++) {
                float4 v = rowp[l + k];
                win[4*k+0] = v.x; win[4*k+1] = v.y;
                win[4*k+2] = v.z; win[4*k+3] = v.w;
            }
        }
        float4 acc = {0.f,0.f,0.f,0.f};
        #pragma unroll
        for (int dd = 0; dd <= 28; dd++) {
            float cw = w[dd < RR ? RR - dd : dd - RR];
            acc.x += cw * win[dd];
            acc.y += cw * win[dd + 1];
            acc.z += cw * win[dd + 2];
            acc.w += cw * win[dd + 3];
        }
        acc.x *= nxi.x; acc.y *= nxi.y; acc.z *= nxi.z; acc.w *= nxi.w;
        tb[c*(PH*32) + (y + RR)*32 + l] = acc;

        // publish own row, then wait only for the 29-row neighborhood
        __syncthreads();
        __threadfence();
        if (tid == 0) atomicAdd(&g_rowflag[y], 1u);
        if (tid < 2*RR + 1) {
            int yy = y - RR + tid;
            if ((unsigned)yy < HH) {
                const unsigned target = base + (unsigned)(it + 1);
                volatile unsigned* pf = &g_rowflag[yy];
                while ((int)(*pf - target) < 0) { }
            }
        }
        __threadfence();
        __syncthreads();

        // blur-y: 29 x LDG.128 (padded rows y..y+28); message lands directly
        float4 a4 = {0.f,0.f,0.f,0.f};
        const float4* col = &tb[c*(PH*32) + y*32 + l];
        #pragma unroll
        for (int dd = 0; dd <= 28; dd++) {
            float4 v = __ldcg(&col[dd*32]);
            float cw = w[dd < RR ? RR - dd : dd - RR];
            a4.x += cw * v.x; a4.y += cw * v.y;
            a4.z += cw * v.z; a4.w += cw * v.w;
        }
        if (it < ITERS-1) {
            q4.x = u4.x - a4.x * nyi; q4.y = u4.y - a4.y * nyi;
            q4.z = u4.z - a4.z * nyi; q4.w = u4.w - a4.w * nyi;
        } else {
            // out layout (1, W, H, C): out[0, x, y, c]
            out[((4*l + 0)*HH + y)*CC + c] = u4.x - a4.x * nyi;
            out[((4*l + 1)*HH + y)*CC + c] = u4.y - a4.y * nyi;
            out[((4*l + 2)*HH + y)*CC + c] = u4.z - a4.z * nyi;
            out[((4*l + 3)*HH + y)*CC + c] = u4.w - a4.w * nyi;
        }
    }
}

extern "C" void kernel_launch(void* const* d_in, const int* in_sizes, int n_in,
                              void* d_out, int out_size) {
    const float* un   = (const float*)d_in[0];
    // d_in[1] (rgb) is dead: reference uses spatial_out for both message terms
    const float* ws   = (const float*)d_in[2];
    const float* wb   = (const float*)d_in[3];
    const float* comp = (const float*)d_in[4];
    crf_persistent<<<NBLK, NTHR>>>(un, ws, wb, comp, (float*)d_out);
}